// round 14
// baseline (speedup 1.0000x reference)
#include <cuda_runtime.h>
#include <cuda_fp16.h>
#include <cstdint>

#define BATCH 4096
#define EMBED 256
#define HEADS 4
#define DH 64
#define HB (HEADS * BATCH)   // 16384
#define NT 64                // keys per tile
#define NTILES (HB / NT)     // 256
#define MROWS 64             // q rows per CTA (2 warps x 32)
#define LDK 72               // padded smem row stride (elems): 144B

// fp16 operands (device globals)
__device__ __align__(16) uint16_t g_qp[HB * DH];
__device__ __align__(16) uint16_t g_kp[HB * DH];
__device__ __align__(16) uint16_t g_vp[HB * DH];

// smem stage layout (bytes): K, V; 2-stage ring
#define ABYTES (64 * LDK * 2)          // 9216 per array
#define OFF_K 0
#define OFF_V (ABYTES)
#define STAGE   (2 * ABYTES)           // 18432
#define SMEM_TOTAL (2 * STAGE)         // 36864

// ---------------------------------------------------------------------------
// helpers
// ---------------------------------------------------------------------------
__device__ __forceinline__ uint32_t smem_u32(const void* p) {
    uint32_t a;
    asm("{ .reg .u64 t; cvta.to.shared.u64 t, %1; cvt.u32.u64 %0, t; }"
        : "=r"(a) : "l"(p));
    return a;
}
__device__ __forceinline__ void mma_f16(float* d, const uint32_t* a,
                                        uint32_t b0, uint32_t b1) {
    asm volatile("mma.sync.aligned.m16n8k16.row.col.f32.f16.f16.f32 "
        "{%0,%1,%2,%3}, {%4,%5,%6,%7}, {%8,%9}, {%0,%1,%2,%3};"
        : "+f"(d[0]), "+f"(d[1]), "+f"(d[2]), "+f"(d[3])
        : "r"(a[0]), "r"(a[1]), "r"(a[2]), "r"(a[3]), "r"(b0), "r"(b1));
}
// pack {upper16 = f16(h), lower16 = f16(l)}
__device__ __forceinline__ uint32_t pack_f16(float h, float l) {
    uint32_t r;
    asm("cvt.rn.f16x2.f32 %0, %1, %2;" : "=r"(r) : "f"(h), "f"(l));
    return r;
}
__device__ __forceinline__ float ex2f(float x) {
    float r;
    asm("ex2.approx.ftz.f32 %0, %1;" : "=f"(r) : "f"(x));
    return r;
}
#define LDSM_X4(r0, r1, r2, r3, addr) \
    asm volatile("ldmatrix.sync.aligned.m8n8.x4.shared.b16 {%0,%1,%2,%3}, [%4];" \
        : "=r"(r0), "=r"(r1), "=r"(r2), "=r"(r3) : "r"(addr))
#define LDSM_X4T(r0, r1, r2, r3, addr) \
    asm volatile("ldmatrix.sync.aligned.m8n8.x4.trans.shared.b16 {%0,%1,%2,%3}, [%4];" \
        : "=r"(r0), "=r"(r1), "=r"(r2), "=r"(r3) : "r"(addr))
#define CP16(dst, src) \
    asm volatile("cp.async.ca.shared.global [%0], [%1], 16;" \
        :: "r"(dst), "l"(src) : "memory")
#define CP_COMMIT() asm volatile("cp.async.commit_group;" ::: "memory")
#define CP_WAIT1()  asm volatile("cp.async.wait_group 1;" ::: "memory")
#define CP_WAIT0()  asm volatile("cp.async.wait_group 0;" ::: "memory")

// ---------------------------------------------------------------------------
// Fused projection: blockIdx.z selects (Q, K, V).
// out[(c>>6)*BATCH + b][c&63] = fp16(scale * sum_k X[b][k] W[k][c])
// ---------------------------------------------------------------------------
__global__ __launch_bounds__(256) void proj_fused_kernel(
    const float* __restrict__ Xq, const float* __restrict__ Xk,
    const float* __restrict__ Xv,
    const float* __restrict__ Wq, const float* __restrict__ Wk,
    const float* __restrict__ Wv,
    uint16_t* __restrict__ Oq, uint16_t* __restrict__ Ok,
    uint16_t* __restrict__ Ov, float qscale)
{
    const int z = blockIdx.z;
    const float* X = (z == 0) ? Xq : (z == 1) ? Xk : Xv;
    const float* W = (z == 0) ? Wq : (z == 1) ? Wk : Wv;
    uint16_t* Ot   = (z == 0) ? Oq : (z == 1) ? Ok : Ov;
    const float scale = (z == 0) ? qscale : 1.0f;

    __shared__ float Xs[16][64];
    __shared__ float Ws[16][64];
    const int tid = threadIdx.x;
    const int tx = tid & 15, ty = tid >> 4;
    const int row0 = blockIdx.x * 64, col0 = blockIdx.y * 64;

    float acc[4][4] = {};
    for (int k0 = 0; k0 < EMBED; k0 += 16) {
        {
            int r = tid >> 2, kq = (tid & 3) * 4;
            float4 v = *(const float4*)(X + (row0 + r) * EMBED + k0 + kq);
            Xs[kq + 0][r] = v.x; Xs[kq + 1][r] = v.y;
            Xs[kq + 2][r] = v.z; Xs[kq + 3][r] = v.w;
        }
        {
            int r = tid >> 4, cq = (tid & 15) * 4;
            *(float4*)(&Ws[r][cq]) =
                *(const float4*)(W + (k0 + r) * (HEADS * DH) + col0 + cq);
        }
        __syncthreads();
        #pragma unroll
        for (int k = 0; k < 16; k++) {
            float4 a = *(float4*)(&Xs[k][ty * 4]);
            float4 b = *(float4*)(&Ws[k][tx * 4]);
            float av[4] = {a.x, a.y, a.z, a.w};
            float bv[4] = {b.x, b.y, b.z, b.w};
            #pragma unroll
            for (int i = 0; i < 4; i++)
                #pragma unroll
                for (int j = 0; j < 4; j++)
                    acc[i][j] += av[i] * bv[j];
        }
        __syncthreads();
    }
    #pragma unroll
    for (int i = 0; i < 4; i++) {
        int b_ = row0 + ty * 4 + i;
        int c = col0 + tx * 4;                      // 4 consecutive cols, same head
        int idx = ((c >> 6) * BATCH + b_) * DH + (c & 63);
        uint16_t h4[4];
        #pragma unroll
        for (int j = 0; j < 4; j++)
            h4[j] = __half_as_ushort(__float2half_rn(acc[i][j] * scale));
        *(uint2*)(Ot + idx) = *(uint2*)h4;
    }
}

// ---------------------------------------------------------------------------
// Flash attention on mma.sync, fp16 single-term, 32 q-rows per warp.
// exp+pack fused into the S loop (minimal live registers).
// Q scale carries 1/8 * log2(e); p = 2^s via raw ex2 (same softmax).
// 2 warps x 32 rows = 64 q rows/CTA; grid 256; 5 CTAs/SM.
// 2-stage cp.async ring.
// ---------------------------------------------------------------------------
__global__ __launch_bounds__(64, 5) void flash_mma_kernel(float* __restrict__ out)
{
    extern __shared__ __align__(16) char smem[];
    const uint32_t sb = smem_u32(smem);

    const int tid = threadIdx.x, lane = tid & 31, w = tid >> 5;
    const int g = lane >> 2, tg = lane & 3;
    const int q0 = blockIdx.x * MROWS;

    // --- persistent Q fragments (fp16), 2 row-groups x 4 ksteps ---
    uint32_t qh[2][4][4];
    #pragma unroll
    for (int rg = 0; rg < 2; rg++) {
        const int ra = q0 + w * 32 + rg * 16 + g, rb = ra + 8;
        const int cb = tg * 2;
        #pragma unroll
        for (int kk = 0; kk < 4; kk++) {
            int c0 = kk * 16 + cb;
            qh[rg][kk][0] = *(const uint32_t*)(g_qp + ra * DH + c0);
            qh[rg][kk][1] = *(const uint32_t*)(g_qp + rb * DH + c0);
            qh[rg][kk][2] = *(const uint32_t*)(g_qp + ra * DH + c0 + 8);
            qh[rg][kk][3] = *(const uint32_t*)(g_qp + rb * DH + c0 + 8);
        }
    }

    // --- tile loader: 64 threads, 512 chunks per array, 16 cp.async each ---
    auto load_tile = [&](int t, int slot) {
        const uint16_t* kb = g_kp + t * NT * DH;
        const uint16_t* vb = g_vp + t * NT * DH;
        uint32_t base = sb + slot * STAGE;
        #pragma unroll
        for (int it = 0; it < 8; it++) {
            int idx = tid + it * 64;               // 0..511
            int r = idx >> 3, e8 = (idx & 7) * 8;  // row, elem offset
            uint32_t d = base + r * (LDK * 2) + e8 * 2;
            CP16(d + OFF_K, kb + r * DH + e8);
            CP16(d + OFF_V, vb + r * DH + e8);
        }
        CP_COMMIT();
    };

    load_tile(0, 0);

    float lA[2] = {0.f, 0.f}, lB[2] = {0.f, 0.f};
    float o[2][8][4];
    #pragma unroll
    for (int rg = 0; rg < 2; rg++)
        #pragma unroll
        for (int j = 0; j < 8; j++)
            #pragma unroll
            for (int i = 0; i < 4; i++) o[rg][j][i] = 0.f;

    for (int t = 0; t < NTILES; t++) {
        __syncthreads();   // all warps done with slot (t+1)&1 (used by tile t-1)
        if (t + 1 < NTILES) { load_tile(t + 1, (t + 1) & 1); CP_WAIT1(); }
        else CP_WAIT0();
        __syncthreads();   // load t visible to all warps
        const uint32_t stg = sb + (t & 1) * STAGE;
        const uint32_t k_b = stg + OFF_K;
        const uint32_t v_b = stg + OFF_V;

        // --- S = Q K^T with fused exp+pack (s dies immediately) ---
        uint32_t pf[2][4][4];
        #pragma unroll
        for (int nt = 0; nt < 8; nt++) {
            float s0[4] = {0.f, 0.f, 0.f, 0.f};
            float s1[4] = {0.f, 0.f, 0.f, 0.f};
            uint32_t bh[4][2];
            #pragma unroll
            for (int p = 0; p < 2; p++) {
                uint32_t off = ((nt * 8 + (lane & 7)) * LDK
                                + p * 32 + ((lane >> 3) & 3) * 8) * 2;
                LDSM_X4(bh[2*p][0], bh[2*p][1], bh[2*p+1][0], bh[2*p+1][1], k_b + off);
            }
            #pragma unroll
            for (int kk = 0; kk < 4; kk++) {
                mma_f16(s0, qh[0][kk], bh[kk][0], bh[kk][1]);
                mma_f16(s1, qh[1][kk], bh[kk][0], bh[kk][1]);
            }
            // p = 2^s; accumulate l; pack to fp16 fragments
            s0[0] = ex2f(s0[0]); s0[1] = ex2f(s0[1]);
            s0[2] = ex2f(s0[2]); s0[3] = ex2f(s0[3]);
            s1[0] = ex2f(s1[0]); s1[1] = ex2f(s1[1]);
            s1[2] = ex2f(s1[2]); s1[3] = ex2f(s1[3]);
            lA[0] += s0[0] + s0[1]; lB[0] += s0[2] + s0[3];
            lA[1] += s1[0] + s1[1]; lB[1] += s1[2] + s1[3];
            const int kk = nt >> 1, base = (nt & 1) * 2;
            pf[0][kk][base + 0] = pack_f16(s0[1], s0[0]);
            pf[0][kk][base + 1] = pack_f16(s0[3], s0[2]);
            pf[1][kk][base + 0] = pack_f16(s1[1], s1[0]);
            pf[1][kk][base + 1] = pack_f16(s1[3], s1[2]);
        }

        // --- O += P V: one V-fragment load feeds both row groups ---
        #pragma unroll
        for (int j = 0; j < 8; j++) {
            uint32_t vh[4][2];
            #pragma unroll
            for (int p = 0; p < 2; p++) {
                uint32_t off = ((p * 32 + lane) * LDK + j * 8) * 2;
                LDSM_X4T(vh[2*p][0], vh[2*p][1], vh[2*p+1][0], vh[2*p+1][1], v_b + off);
            }
            #pragma unroll
            for (int kk = 0; kk < 4; kk++) {
                mma_f16(o[0][j], pf[0][kk], vh[kk][0], vh[kk][1]);
                mma_f16(o[1][j], pf[1][kk], vh[kk][0], vh[kk][1]);
            }
        }
    }

    // --- epilogue: quad-reduce l, normalize, merge heads ---
    #pragma unroll
    for (int rg = 0; rg < 2; rg++) {
        float la = lA[rg], lb = lB[rg];
        la += __shfl_xor_sync(0xffffffffu, la, 1);
        la += __shfl_xor_sync(0xffffffffu, la, 2);
        lb += __shfl_xor_sync(0xffffffffu, lb, 1);
        lb += __shfl_xor_sync(0xffffffffu, lb, 2);
        const float iA = 1.f / la, iB = 1.f / lb;
        const int rA = q0 + w * 32 + rg * 16 + g, rB = rA + 8;
        float* dA = out + (rA & (BATCH - 1)) * (HEADS * DH) + (rA >> 12) * DH;
        float* dB = out + (rB & (BATCH - 1)) * (HEADS * DH) + (rB >> 12) * DH;
        #pragma unroll
        for (int j = 0; j < 8; j++) {
            int c = j * 8 + tg * 2;
            dA[c] = o[rg][j][0] * iA; dA[c + 1] = o[rg][j][1] * iA;
            dB[c] = o[rg][j][2] * iB; dB[c + 1] = o[rg][j][3] * iB;
        }
    }
}

extern "C" void kernel_launch(void* const* d_in, const int* in_sizes, int n_in,
                              void* d_out, int out_size)
{
    const float* q  = (const float*)d_in[0];
    const float* k  = (const float*)d_in[1];
    const float* v  = (const float*)d_in[2];
    const float* wq = (const float*)d_in[3];
    const float* wk = (const float*)d_in[4];
    const float* wv = (const float*)d_in[5];
    float* out = (float*)d_out;

    uint16_t *qp, *kp, *vp;
    cudaGetSymbolAddress((void**)&qp, g_qp);
    cudaGetSymbolAddress((void**)&kp, g_kp);
    cudaGetSymbolAddress((void**)&vp, g_vp);

    cudaFuncSetAttribute(flash_mma_kernel,
                         cudaFuncAttributeMaxDynamicSharedMemorySize, SMEM_TOTAL);

    // Q scale = 1/sqrt(64) * log2(e): softmax via 2^s is identical to e^s
    dim3 pgrid(BATCH / 64, (HEADS * DH) / 64, 3);
    proj_fused_kernel<<<pgrid, 256>>>(q, k, v, wq, wk, wv, qp, kp, vp,
                                      0.125f * 1.44269504f);

    flash_mma_kernel<<<HB / MROWS, 64, SMEM_TOTAL>>>(out);
}

// round 16
// speedup vs baseline: 1.3045x; 1.3045x over previous
#include <cuda_runtime.h>
#include <cuda_fp16.h>
#include <cstdint>

#define BATCH 4096
#define EMBED 256
#define HEADS 4
#define DH 64
#define HB (HEADS * BATCH)   // 16384
#define NT 64                // keys per tile
#define NTILES (HB / NT)     // 256
#define KS 4                 // key splits
#define TILES_PER (NTILES / KS)  // 64
#define MROWS 64             // q rows per CTA (2 warps x 32)
#define LDK 72               // padded smem row stride (elems): 144B

// fp16 operands (device globals)
__device__ __align__(16) uint16_t g_qp[HB * DH];
__device__ __align__(16) uint16_t g_kp[HB * DH];
__device__ __align__(16) uint16_t g_vp[HB * DH];
// split-K partial accumulators
__device__ __align__(16) float g_opart[KS * HB * DH];   // 16 MB
__device__ __align__(16) float g_lpart[KS * HB];

// smem stage layout (bytes): K, V; 3-stage ring
#define ABYTES (64 * LDK * 2)          // 9216 per array
#define OFF_K 0
#define OFF_V (ABYTES)
#define STAGE   (2 * ABYTES)           // 18432
#define SMEM_TOTAL (3 * STAGE)         // 55296

// ---------------------------------------------------------------------------
// helpers
// ---------------------------------------------------------------------------
__device__ __forceinline__ uint32_t smem_u32(const void* p) {
    uint32_t a;
    asm("{ .reg .u64 t; cvta.to.shared.u64 t, %1; cvt.u32.u64 %0, t; }"
        : "=r"(a) : "l"(p));
    return a;
}
__device__ __forceinline__ void mma_f16(float* d, const uint32_t* a,
                                        uint32_t b0, uint32_t b1) {
    asm volatile("mma.sync.aligned.m16n8k16.row.col.f32.f16.f16.f32 "
        "{%0,%1,%2,%3}, {%4,%5,%6,%7}, {%8,%9}, {%0,%1,%2,%3};"
        : "+f"(d[0]), "+f"(d[1]), "+f"(d[2]), "+f"(d[3])
        : "r"(a[0]), "r"(a[1]), "r"(a[2]), "r"(a[3]), "r"(b0), "r"(b1));
}
// pack {upper16 = f16(h), lower16 = f16(l)}
__device__ __forceinline__ uint32_t pack_f16(float h, float l) {
    uint32_t r;
    asm("cvt.rn.f16x2.f32 %0, %1, %2;" : "=r"(r) : "f"(h), "f"(l));
    return r;
}
__device__ __forceinline__ float ex2f(float x) {
    float r;
    asm("ex2.approx.ftz.f32 %0, %1;" : "=f"(r) : "f"(x));
    return r;
}
#define LDSM_X4(r0, r1, r2, r3, addr) \
    asm volatile("ldmatrix.sync.aligned.m8n8.x4.shared.b16 {%0,%1,%2,%3}, [%4];" \
        : "=r"(r0), "=r"(r1), "=r"(r2), "=r"(r3) : "r"(addr))
#define LDSM_X4T(r0, r1, r2, r3, addr) \
    asm volatile("ldmatrix.sync.aligned.m8n8.x4.trans.shared.b16 {%0,%1,%2,%3}, [%4];" \
        : "=r"(r0), "=r"(r1), "=r"(r2), "=r"(r3) : "r"(addr))
#define CP16(dst, src) \
    asm volatile("cp.async.ca.shared.global [%0], [%1], 16;" \
        :: "r"(dst), "l"(src) : "memory")
#define CP_COMMIT() asm volatile("cp.async.commit_group;" ::: "memory")
#define CP_WAIT1()  asm volatile("cp.async.wait_group 1;" ::: "memory")
#define CP_WAIT0()  asm volatile("cp.async.wait_group 0;" ::: "memory")

// ---------------------------------------------------------------------------
// Fused projection: blockIdx.z selects (Q, K, V).
// out[(c>>6)*BATCH + b][c&63] = fp16(scale * sum_k X[b][k] W[k][c])
// ---------------------------------------------------------------------------
__global__ __launch_bounds__(256) void proj_fused_kernel(
    const float* __restrict__ Xq, const float* __restrict__ Xk,
    const float* __restrict__ Xv,
    const float* __restrict__ Wq, const float* __restrict__ Wk,
    const float* __restrict__ Wv,
    uint16_t* __restrict__ Oq, uint16_t* __restrict__ Ok,
    uint16_t* __restrict__ Ov, float qscale)
{
    const int z = blockIdx.z;
    const float* X = (z == 0) ? Xq : (z == 1) ? Xk : Xv;
    const float* W = (z == 0) ? Wq : (z == 1) ? Wk : Wv;
    uint16_t* Ot   = (z == 0) ? Oq : (z == 1) ? Ok : Ov;
    const float scale = (z == 0) ? qscale : 1.0f;

    __shared__ float Xs[16][64];
    __shared__ float Ws[16][64];
    const int tid = threadIdx.x;
    const int tx = tid & 15, ty = tid >> 4;
    const int row0 = blockIdx.x * 64, col0 = blockIdx.y * 64;

    float acc[4][4] = {};
    for (int k0 = 0; k0 < EMBED; k0 += 16) {
        {
            int r = tid >> 2, kq = (tid & 3) * 4;
            float4 v = *(const float4*)(X + (row0 + r) * EMBED + k0 + kq);
            Xs[kq + 0][r] = v.x; Xs[kq + 1][r] = v.y;
            Xs[kq + 2][r] = v.z; Xs[kq + 3][r] = v.w;
        }
        {
            int r = tid >> 4, cq = (tid & 15) * 4;
            *(float4*)(&Ws[r][cq]) =
                *(const float4*)(W + (k0 + r) * (HEADS * DH) + col0 + cq);
        }
        __syncthreads();
        #pragma unroll
        for (int k = 0; k < 16; k++) {
            float4 a = *(float4*)(&Xs[k][ty * 4]);
            float4 b = *(float4*)(&Ws[k][tx * 4]);
            float av[4] = {a.x, a.y, a.z, a.w};
            float bv[4] = {b.x, b.y, b.z, b.w};
            #pragma unroll
            for (int i = 0; i < 4; i++)
                #pragma unroll
                for (int j = 0; j < 4; j++)
                    acc[i][j] += av[i] * bv[j];
        }
        __syncthreads();
    }
    #pragma unroll
    for (int i = 0; i < 4; i++) {
        int b_ = row0 + ty * 4 + i;
        int c = col0 + tx * 4;                      // 4 consecutive cols, same head
        int idx = ((c >> 6) * BATCH + b_) * DH + (c & 63);
        uint16_t h4[4];
        #pragma unroll
        for (int j = 0; j < 4; j++)
            h4[j] = __half_as_ushort(__float2half_rn(acc[i][j] * scale));
        *(uint2*)(Ot + idx) = *(uint2*)h4;
    }
}

// ---------------------------------------------------------------------------
// Split-K flash: blockIdx.x = q-block, blockIdx.y = key split.
// Unshifted softmax => partial O and l over disjoint key ranges add linearly.
// fp16 single-term S & PV, 32 q-rows/warp, fused exp+pack.
// 3-stage cp.async ring, ONE __syncthreads per tile (R13 structure).
// ---------------------------------------------------------------------------
__global__ __launch_bounds__(64, 4) void flash_mma_kernel()
{
    extern __shared__ __align__(16) char smem[];
    const uint32_t sb = smem_u32(smem);

    const int tid = threadIdx.x, lane = tid & 31, w = tid >> 5;
    const int g = lane >> 2, tg = lane & 3;
    const int q0 = blockIdx.x * MROWS;
    const int ks = blockIdx.y;
    const int t0 = ks * TILES_PER;

    // --- persistent Q fragments (fp16), 2 row-groups x 4 ksteps ---
    uint32_t qh[2][4][4];
    #pragma unroll
    for (int rg = 0; rg < 2; rg++) {
        const int ra = q0 + w * 32 + rg * 16 + g, rb = ra + 8;
        const int cb = tg * 2;
        #pragma unroll
        for (int kk = 0; kk < 4; kk++) {
            int c0 = kk * 16 + cb;
            qh[rg][kk][0] = *(const uint32_t*)(g_qp + ra * DH + c0);
            qh[rg][kk][1] = *(const uint32_t*)(g_qp + rb * DH + c0);
            qh[rg][kk][2] = *(const uint32_t*)(g_qp + ra * DH + c0 + 8);
            qh[rg][kk][3] = *(const uint32_t*)(g_qp + rb * DH + c0 + 8);
        }
    }

    // --- tile loader: 64 threads, 512 chunks per array, 16 cp.async each ---
    auto load_tile = [&](int t, int slot) {
        const uint16_t* kb = g_kp + t * NT * DH;
        const uint16_t* vb = g_vp + t * NT * DH;
        uint32_t base = sb + slot * STAGE;
        #pragma unroll
        for (int it = 0; it < 8; it++) {
            int idx = tid + it * 64;               // 0..511
            int r = idx >> 3, e8 = (idx & 7) * 8;  // row, elem offset
            uint32_t d = base + r * (LDK * 2) + e8 * 2;
            CP16(d + OFF_K, kb + r * DH + e8);
            CP16(d + OFF_V, vb + r * DH + e8);
        }
        CP_COMMIT();
    };

    load_tile(t0, 0);
    load_tile(t0 + 1, 1);

    float lA[2] = {0.f, 0.f}, lB[2] = {0.f, 0.f};
    float o[2][8][4];
    #pragma unroll
    for (int rg = 0; rg < 2; rg++)
        #pragma unroll
        for (int j = 0; j < 8; j++)
            #pragma unroll
            for (int i = 0; i < 4; i++) o[rg][j][i] = 0.f;

    int slot = 0;
    for (int tt = 0; tt < TILES_PER; tt++) {
        if (tt >= TILES_PER - 2) CP_WAIT0(); else CP_WAIT1();
        __syncthreads();   // also guards slot overwrite by the load below
        if (tt + 2 < TILES_PER) {
            int ns = slot + 2; if (ns >= 3) ns -= 3;
            load_tile(t0 + tt + 2, ns);
        }
        const uint32_t stg = sb + slot * STAGE;
        const uint32_t k_b = stg + OFF_K;
        const uint32_t v_b = stg + OFF_V;
        slot = (slot + 1 == 3) ? 0 : slot + 1;

        // --- S = Q K^T with fused exp+pack (s dies immediately) ---
        uint32_t pf[2][4][4];
        #pragma unroll
        for (int nt = 0; nt < 8; nt++) {
            float s0[4] = {0.f, 0.f, 0.f, 0.f};
            float s1[4] = {0.f, 0.f, 0.f, 0.f};
            uint32_t bh[4][2];
            #pragma unroll
            for (int p = 0; p < 2; p++) {
                uint32_t off = ((nt * 8 + (lane & 7)) * LDK
                                + p * 32 + ((lane >> 3) & 3) * 8) * 2;
                LDSM_X4(bh[2*p][0], bh[2*p][1], bh[2*p+1][0], bh[2*p+1][1], k_b + off);
            }
            #pragma unroll
            for (int kk = 0; kk < 4; kk++) {
                mma_f16(s0, qh[0][kk], bh[kk][0], bh[kk][1]);
                mma_f16(s1, qh[1][kk], bh[kk][0], bh[kk][1]);
            }
            // p = 2^s; accumulate l; pack to fp16 fragments
            s0[0] = ex2f(s0[0]); s0[1] = ex2f(s0[1]);
            s0[2] = ex2f(s0[2]); s0[3] = ex2f(s0[3]);
            s1[0] = ex2f(s1[0]); s1[1] = ex2f(s1[1]);
            s1[2] = ex2f(s1[2]); s1[3] = ex2f(s1[3]);
            lA[0] += s0[0] + s0[1]; lB[0] += s0[2] + s0[3];
            lA[1] += s1[0] + s1[1]; lB[1] += s1[2] + s1[3];
            const int kk = nt >> 1, base = (nt & 1) * 2;
            pf[0][kk][base + 0] = pack_f16(s0[1], s0[0]);
            pf[0][kk][base + 1] = pack_f16(s0[3], s0[2]);
            pf[1][kk][base + 0] = pack_f16(s1[1], s1[0]);
            pf[1][kk][base + 1] = pack_f16(s1[3], s1[2]);
        }

        // --- O += P V: one V-fragment load feeds both row groups ---
        #pragma unroll
        for (int j = 0; j < 8; j++) {
            uint32_t vh[4][2];
            #pragma unroll
            for (int p = 0; p < 2; p++) {
                uint32_t off = ((p * 32 + lane) * LDK + j * 8) * 2;
                LDSM_X4T(vh[2*p][0], vh[2*p][1], vh[2*p+1][0], vh[2*p+1][1], v_b + off);
            }
            #pragma unroll
            for (int kk = 0; kk < 4; kk++) {
                mma_f16(o[0][j], pf[0][kk], vh[kk][0], vh[kk][1]);
                mma_f16(o[1][j], pf[1][kk], vh[kk][0], vh[kk][1]);
            }
        }
        // no trailing sync: next iteration's top barrier guards reuse
    }

    // --- epilogue: write partial O and l (no normalization here) ---
    float* opart = g_opart + (size_t)ks * HB * DH;
    float* lpart = g_lpart + ks * HB;
    #pragma unroll
    for (int rg = 0; rg < 2; rg++) {
        float la = lA[rg], lb = lB[rg];
        la += __shfl_xor_sync(0xffffffffu, la, 1);
        la += __shfl_xor_sync(0xffffffffu, la, 2);
        lb += __shfl_xor_sync(0xffffffffu, lb, 1);
        lb += __shfl_xor_sync(0xffffffffu, lb, 2);
        const int rA = q0 + w * 32 + rg * 16 + g, rB = rA + 8;
        if (tg == 0) { lpart[rA] = la; lpart[rB] = lb; }
        #pragma unroll
        for (int j = 0; j < 8; j++) {
            int c = j * 8 + tg * 2;
            opart[rA * DH + c]     = o[rg][j][0];
            opart[rA * DH + c + 1] = o[rg][j][1];
            opart[rB * DH + c]     = o[rg][j][2];
            opart[rB * DH + c + 1] = o[rg][j][3];
        }
    }
}

// ---------------------------------------------------------------------------
// Combine: out[b][h*64+c] = (sum_ks O_part) / (sum_ks l_part), merge heads.
// ---------------------------------------------------------------------------
__global__ __launch_bounds__(256) void combine_kernel(float* __restrict__ out)
{
    int idx = blockIdx.x * 256 + threadIdx.x;     // 0 .. HB*DH/2 - 1 (float2)
    int row = idx >> 5;                            // DH/2 float2 per row
    int c2 = (idx & 31) * 2;
    float l = 0.f;
    #pragma unroll
    for (int ks = 0; ks < KS; ks++) l += g_lpart[ks * HB + row];
    float2 acc = make_float2(0.f, 0.f);
    #pragma unroll
    for (int ks = 0; ks < KS; ks++) {
        float2 v = *(const float2*)(g_opart + ((size_t)ks * HB + row) * DH + c2);
        acc.x += v.x; acc.y += v.y;
    }
    float inv = 1.f / l;
    int h = row >> 12, b = row & (BATCH - 1);
    float2 r = make_float2(acc.x * inv, acc.y * inv);
    *(float2*)(out + b * (HEADS * DH) + h * DH + c2) = r;
}

extern "C" void kernel_launch(void* const* d_in, const int* in_sizes, int n_in,
                              void* d_out, int out_size)
{
    const float* q  = (const float*)d_in[0];
    const float* k  = (const float*)d_in[1];
    const float* v  = (const float*)d_in[2];
    const float* wq = (const float*)d_in[3];
    const float* wk = (const float*)d_in[4];
    const float* wv = (const float*)d_in[5];
    float* out = (float*)d_out;

    uint16_t *qp, *kp, *vp;
    cudaGetSymbolAddress((void**)&qp, g_qp);
    cudaGetSymbolAddress((void**)&kp, g_kp);
    cudaGetSymbolAddress((void**)&vp, g_vp);

    cudaFuncSetAttribute(flash_mma_kernel,
                         cudaFuncAttributeMaxDynamicSharedMemorySize, SMEM_TOTAL);

    // Q scale = 1/sqrt(64) * log2(e): softmax via 2^s is identical to e^s
    dim3 pgrid(BATCH / 64, (HEADS * DH) / 64, 3);
    proj_fused_kernel<<<pgrid, 256>>>(q, k, v, wq, wk, wv, qp, kp, vp,
                                      0.125f * 1.44269504f);

    dim3 fgrid(HB / MROWS, KS);
    flash_mma_kernel<<<fgrid, 64, SMEM_TOTAL>>>();

    combine_kernel<<<(HB * DH / 2) / 256, 256>>>(out);
}

// round 17
// speedup vs baseline: 1.5169x; 1.1628x over previous
#include <cuda_runtime.h>
#include <cuda_fp16.h>
#include <cstdint>

#define BATCH 4096
#define EMBED 256
#define HEADS 4
#define DH 64
#define HB (HEADS * BATCH)   // 16384
#define NT 64                // keys per tile
#define NTILES (HB / NT)     // 256
#define KS 4                 // key splits
#define TILES_PER (NTILES / KS)  // 64
#define MROWS 64             // q rows per CTA (2 warps x 32)
#define LDK 72               // padded smem row stride (elems): 144B

// fp16 operands (device globals)
__device__ __align__(16) uint16_t g_qp[HB * DH];
__device__ __align__(16) uint16_t g_kp[HB * DH];
__device__ __align__(16) uint16_t g_vp[HB * DH];
// fp16 copies of inputs (for tensor-core projection)
__device__ __align__(16) uint16_t g_x16[3][BATCH * EMBED];
__device__ __align__(16) uint16_t g_w16[3][EMBED * EMBED];
// split-K partial accumulators
__device__ __align__(16) float g_opart[KS * HB * DH];   // 16 MB
__device__ __align__(16) float g_lpart[KS * HB];

// smem stage layout (bytes): K, V; 3-stage ring
#define ABYTES (64 * LDK * 2)          // 9216 per array
#define OFF_K 0
#define OFF_V (ABYTES)
#define STAGE   (2 * ABYTES)           // 18432
#define SMEM_TOTAL (3 * STAGE)         // 55296

// ---------------------------------------------------------------------------
// helpers
// ---------------------------------------------------------------------------
__device__ __forceinline__ uint32_t smem_u32(const void* p) {
    uint32_t a;
    asm("{ .reg .u64 t; cvta.to.shared.u64 t, %1; cvt.u32.u64 %0, t; }"
        : "=r"(a) : "l"(p));
    return a;
}
__device__ __forceinline__ void mma_f16(float* d, const uint32_t* a,
                                        uint32_t b0, uint32_t b1) {
    asm volatile("mma.sync.aligned.m16n8k16.row.col.f32.f16.f16.f32 "
        "{%0,%1,%2,%3}, {%4,%5,%6,%7}, {%8,%9}, {%0,%1,%2,%3};"
        : "+f"(d[0]), "+f"(d[1]), "+f"(d[2]), "+f"(d[3])
        : "r"(a[0]), "r"(a[1]), "r"(a[2]), "r"(a[3]), "r"(b0), "r"(b1));
}
// pack {upper16 = f16(h), lower16 = f16(l)}
__device__ __forceinline__ uint32_t pack_f16(float h, float l) {
    uint32_t r;
    asm("cvt.rn.f16x2.f32 %0, %1, %2;" : "=r"(r) : "f"(h), "f"(l));
    return r;
}
__device__ __forceinline__ float ex2f(float x) {
    float r;
    asm("ex2.approx.ftz.f32 %0, %1;" : "=f"(r) : "f"(x));
    return r;
}
#define LDSM_X4(r0, r1, r2, r3, addr) \
    asm volatile("ldmatrix.sync.aligned.m8n8.x4.shared.b16 {%0,%1,%2,%3}, [%4];" \
        : "=r"(r0), "=r"(r1), "=r"(r2), "=r"(r3) : "r"(addr))
#define LDSM_X4T(r0, r1, r2, r3, addr) \
    asm volatile("ldmatrix.sync.aligned.m8n8.x4.trans.shared.b16 {%0,%1,%2,%3}, [%4];" \
        : "=r"(r0), "=r"(r1), "=r"(r2), "=r"(r3) : "r"(addr))
#define CP16(dst, src) \
    asm volatile("cp.async.ca.shared.global [%0], [%1], 16;" \
        :: "r"(dst), "l"(src) : "memory")
#define CP_COMMIT() asm volatile("cp.async.commit_group;" ::: "memory")
#define CP_WAIT1()  asm volatile("cp.async.wait_group 1;" ::: "memory")
#define CP_WAIT0()  asm volatile("cp.async.wait_group 0;" ::: "memory")

// ---------------------------------------------------------------------------
// Convert inputs to fp16: X (q,k,v) and W (wq,wk,wv). qscale*log2(e) folded
// into Wq (linear in W, so identical semantics).
// blockIdx.y: 0-2 = X[z], 3-5 = W[z-3]. 4 floats per thread.
// ---------------------------------------------------------------------------
__global__ __launch_bounds__(256) void convert_kernel(
    const float* __restrict__ xq, const float* __restrict__ xk,
    const float* __restrict__ xv,
    const float* __restrict__ wq, const float* __restrict__ wk,
    const float* __restrict__ wv, float qscale)
{
    const int z = blockIdx.y;
    const float* src; uint16_t* dst; int n; float scale = 1.0f;
    if (z < 3) {
        src = (z == 0) ? xq : (z == 1) ? xk : xv;
        dst = g_x16[z]; n = BATCH * EMBED;
    } else {
        src = (z == 3) ? wq : (z == 4) ? wk : wv;
        dst = g_w16[z - 3]; n = EMBED * EMBED;
        if (z == 3) scale = qscale;
    }
    int idx = (blockIdx.x * 256 + threadIdx.x) * 4;
    if (idx >= n) return;
    float4 v = *(const float4*)(src + idx);
    uint32_t p0 = pack_f16(v.y * scale, v.x * scale);
    uint32_t p1 = pack_f16(v.w * scale, v.z * scale);
    *(uint2*)(dst + idx) = make_uint2(p0, p1);
}

// ---------------------------------------------------------------------------
// Tensor-core projection: C[64 rows x 64 cols] per CTA, K=256 in 4 chunks.
// A = X fp16 (gmem frags, flash-Q pattern); B = W [k][n] smem via LDSM_X4T
// (flash-V pattern). Output written fp16 in split-head layout.
// blockIdx.x: row block, blockIdx.y: col block (=head), blockIdx.z: q/k/v.
// ---------------------------------------------------------------------------
__global__ __launch_bounds__(64) void proj_mma_kernel()
{
    __shared__ __align__(16) uint16_t Wt[EMBED * LDK];

    const int tid = threadIdx.x, lane = tid & 31, w = tid >> 5;
    const int g = lane >> 2, tg = lane & 3;
    const int row0 = blockIdx.x * 64;
    const int col0 = blockIdx.y * 64;
    const int z = blockIdx.z;
    const uint16_t* X = g_x16[z];
    const uint16_t* W = g_w16[z];
    uint16_t* O = (z == 0) ? g_qp : (z == 1) ? g_kp : g_vp;

    // --- load W column tile [256 k][64 n] into smem (padded stride) ---
    for (int it = 0; it < 32; it++) {
        int idx = tid + it * 64;                  // 0..2047
        int r = idx >> 3, e8 = (idx & 7) * 8;
        *(uint4*)(Wt + r * LDK + e8) = *(const uint4*)(W + r * EMBED + col0 + e8);
    }
    __syncthreads();
    const uint32_t wb = smem_u32(Wt);

    float o[2][8][4];
    #pragma unroll
    for (int rg = 0; rg < 2; rg++)
        #pragma unroll
        for (int j = 0; j < 8; j++)
            #pragma unroll
            for (int i = 0; i < 4; i++) o[rg][j][i] = 0.f;

    for (int chunk = 0; chunk < 4; chunk++) {
        // A fragments from gmem fp16 (flash-Q pattern), rows of this chunk's K
        uint32_t ax[2][4][4];
        #pragma unroll
        for (int rg = 0; rg < 2; rg++) {
            const int ra = row0 + w * 32 + rg * 16 + g, rb = ra + 8;
            #pragma unroll
            for (int kk = 0; kk < 4; kk++) {
                int c0 = chunk * 64 + kk * 16 + tg * 2;
                ax[rg][kk][0] = *(const uint32_t*)(X + ra * EMBED + c0);
                ax[rg][kk][1] = *(const uint32_t*)(X + rb * EMBED + c0);
                ax[rg][kk][2] = *(const uint32_t*)(X + ra * EMBED + c0 + 8);
                ax[rg][kk][3] = *(const uint32_t*)(X + rb * EMBED + c0 + 8);
            }
        }
        #pragma unroll
        for (int j = 0; j < 8; j++) {
            uint32_t bh[4][2];
            #pragma unroll
            for (int p = 0; p < 2; p++) {
                uint32_t off = ((chunk * 64 + p * 32 + lane) * LDK + j * 8) * 2;
                LDSM_X4T(bh[2*p][0], bh[2*p][1], bh[2*p+1][0], bh[2*p+1][1], wb + off);
            }
            #pragma unroll
            for (int kk = 0; kk < 4; kk++) {
                mma_f16(o[0][j], ax[0][kk], bh[kk][0], bh[kk][1]);
                mma_f16(o[1][j], ax[1][kk], bh[kk][0], bh[kk][1]);
            }
        }
    }

    // --- epilogue: fp16 round, split-head layout [head*BATCH + b][c&63] ---
    #pragma unroll
    for (int rg = 0; rg < 2; rg++) {
        const int rA = row0 + w * 32 + rg * 16 + g, rB = rA + 8;
        uint16_t* dA = O + ((size_t)blockIdx.y * BATCH + rA) * DH;
        uint16_t* dB = O + ((size_t)blockIdx.y * BATCH + rB) * DH;
        #pragma unroll
        for (int j = 0; j < 8; j++) {
            int cc = j * 8 + tg * 2;
            *(uint32_t*)(dA + cc) = pack_f16(o[rg][j][1], o[rg][j][0]);
            *(uint32_t*)(dB + cc) = pack_f16(o[rg][j][3], o[rg][j][2]);
        }
    }
}

// ---------------------------------------------------------------------------
// Split-K flash: blockIdx.x = q-block, blockIdx.y = key split.
// Unshifted softmax => partial O and l over disjoint key ranges add linearly.
// fp16 single-term S & PV, 32 q-rows/warp, fused exp+pack.
// 3-stage cp.async ring, ONE __syncthreads per tile.
// ---------------------------------------------------------------------------
__global__ __launch_bounds__(64, 4) void flash_mma_kernel()
{
    extern __shared__ __align__(16) char smem[];
    const uint32_t sb = smem_u32(smem);

    const int tid = threadIdx.x, lane = tid & 31, w = tid >> 5;
    const int g = lane >> 2, tg = lane & 3;
    const int q0 = blockIdx.x * MROWS;
    const int ks = blockIdx.y;
    const int t0 = ks * TILES_PER;

    // --- persistent Q fragments (fp16), 2 row-groups x 4 ksteps ---
    uint32_t qh[2][4][4];
    #pragma unroll
    for (int rg = 0; rg < 2; rg++) {
        const int ra = q0 + w * 32 + rg * 16 + g, rb = ra + 8;
        const int cb = tg * 2;
        #pragma unroll
        for (int kk = 0; kk < 4; kk++) {
            int c0 = kk * 16 + cb;
            qh[rg][kk][0] = *(const uint32_t*)(g_qp + ra * DH + c0);
            qh[rg][kk][1] = *(const uint32_t*)(g_qp + rb * DH + c0);
            qh[rg][kk][2] = *(const uint32_t*)(g_qp + ra * DH + c0 + 8);
            qh[rg][kk][3] = *(const uint32_t*)(g_qp + rb * DH + c0 + 8);
        }
    }

    // --- tile loader: 64 threads, 512 chunks per array, 16 cp.async each ---
    auto load_tile = [&](int t, int slot) {
        const uint16_t* kb = g_kp + t * NT * DH;
        const uint16_t* vb = g_vp + t * NT * DH;
        uint32_t base = sb + slot * STAGE;
        #pragma unroll
        for (int it = 0; it < 8; it++) {
            int idx = tid + it * 64;               // 0..511
            int r = idx >> 3, e8 = (idx & 7) * 8;  // row, elem offset
            uint32_t d = base + r * (LDK * 2) + e8 * 2;
            CP16(d + OFF_K, kb + r * DH + e8);
            CP16(d + OFF_V, vb + r * DH + e8);
        }
        CP_COMMIT();
    };

    load_tile(t0, 0);
    load_tile(t0 + 1, 1);

    float lA[2] = {0.f, 0.f}, lB[2] = {0.f, 0.f};
    float o[2][8][4];
    #pragma unroll
    for (int rg = 0; rg < 2; rg++)
        #pragma unroll
        for (int j = 0; j < 8; j++)
            #pragma unroll
            for (int i = 0; i < 4; i++) o[rg][j][i] = 0.f;

    int slot = 0;
    for (int tt = 0; tt < TILES_PER; tt++) {
        if (tt >= TILES_PER - 2) CP_WAIT0(); else CP_WAIT1();
        __syncthreads();   // also guards slot overwrite by the load below
        if (tt + 2 < TILES_PER) {
            int ns = slot + 2; if (ns >= 3) ns -= 3;
            load_tile(t0 + tt + 2, ns);
        }
        const uint32_t stg = sb + slot * STAGE;
        const uint32_t k_b = stg + OFF_K;
        const uint32_t v_b = stg + OFF_V;
        slot = (slot + 1 == 3) ? 0 : slot + 1;

        // --- S = Q K^T with fused exp+pack (s dies immediately) ---
        uint32_t pf[2][4][4];
        #pragma unroll
        for (int nt = 0; nt < 8; nt++) {
            float s0[4] = {0.f, 0.f, 0.f, 0.f};
            float s1[4] = {0.f, 0.f, 0.f, 0.f};
            uint32_t bh[4][2];
            #pragma unroll
            for (int p = 0; p < 2; p++) {
                uint32_t off = ((nt * 8 + (lane & 7)) * LDK
                                + p * 32 + ((lane >> 3) & 3) * 8) * 2;
                LDSM_X4(bh[2*p][0], bh[2*p][1], bh[2*p+1][0], bh[2*p+1][1], k_b + off);
            }
            #pragma unroll
            for (int kk = 0; kk < 4; kk++) {
                mma_f16(s0, qh[0][kk], bh[kk][0], bh[kk][1]);
                mma_f16(s1, qh[1][kk], bh[kk][0], bh[kk][1]);
            }
            // p = 2^s; accumulate l; pack to fp16 fragments
            s0[0] = ex2f(s0[0]); s0[1] = ex2f(s0[1]);
            s0[2] = ex2f(s0[2]); s0[3] = ex2f(s0[3]);
            s1[0] = ex2f(s1[0]); s1[1] = ex2f(s1[1]);
            s1[2] = ex2f(s1[2]); s1[3] = ex2f(s1[3]);
            lA[0] += s0[0] + s0[1]; lB[0] += s0[2] + s0[3];
            lA[1] += s1[0] + s1[1]; lB[1] += s1[2] + s1[3];
            const int kk = nt >> 1, base = (nt & 1) * 2;
            pf[0][kk][base + 0] = pack_f16(s0[1], s0[0]);
            pf[0][kk][base + 1] = pack_f16(s0[3], s0[2]);
            pf[1][kk][base + 0] = pack_f16(s1[1], s1[0]);
            pf[1][kk][base + 1] = pack_f16(s1[3], s1[2]);
        }

        // --- O += P V: one V-fragment load feeds both row groups ---
        #pragma unroll
        for (int j = 0; j < 8; j++) {
            uint32_t vh[4][2];
            #pragma unroll
            for (int p = 0; p < 2; p++) {
                uint32_t off = ((p * 32 + lane) * LDK + j * 8) * 2;
                LDSM_X4T(vh[2*p][0], vh[2*p][1], vh[2*p+1][0], vh[2*p+1][1], v_b + off);
            }
            #pragma unroll
            for (int kk = 0; kk < 4; kk++) {
                mma_f16(o[0][j], pf[0][kk], vh[kk][0], vh[kk][1]);
                mma_f16(o[1][j], pf[1][kk], vh[kk][0], vh[kk][1]);
            }
        }
        // no trailing sync: next iteration's top barrier guards reuse
    }

    // --- epilogue: write partial O and l (no normalization here) ---
    float* opart = g_opart + (size_t)ks * HB * DH;
    float* lpart = g_lpart + ks * HB;
    #pragma unroll
    for (int rg = 0; rg < 2; rg++) {
        float la = lA[rg], lb = lB[rg];
        la += __shfl_xor_sync(0xffffffffu, la, 1);
        la += __shfl_xor_sync(0xffffffffu, la, 2);
        lb += __shfl_xor_sync(0xffffffffu, lb, 1);
        lb += __shfl_xor_sync(0xffffffffu, lb, 2);
        const int rA = q0 + w * 32 + rg * 16 + g, rB = rA + 8;
        if (tg == 0) { lpart[rA] = la; lpart[rB] = lb; }
        #pragma unroll
        for (int j = 0; j < 8; j++) {
            int c = j * 8 + tg * 2;
            opart[rA * DH + c]     = o[rg][j][0];
            opart[rA * DH + c + 1] = o[rg][j][1];
            opart[rB * DH + c]     = o[rg][j][2];
            opart[rB * DH + c + 1] = o[rg][j][3];
        }
    }
}

// ---------------------------------------------------------------------------
// Combine: out[b][h*64+c] = (sum_ks O_part) / (sum_ks l_part), merge heads.
// ---------------------------------------------------------------------------
__global__ __launch_bounds__(256) void combine_kernel(float* __restrict__ out)
{
    int idx = blockIdx.x * 256 + threadIdx.x;     // 0 .. HB*DH/2 - 1 (float2)
    int row = idx >> 5;                            // DH/2 float2 per row
    int c2 = (idx & 31) * 2;
    float l = 0.f;
    #pragma unroll
    for (int ks = 0; ks < KS; ks++) l += g_lpart[ks * HB + row];
    float2 acc = make_float2(0.f, 0.f);
    #pragma unroll
    for (int ks = 0; ks < KS; ks++) {
        float2 v = *(const float2*)(g_opart + ((size_t)ks * HB + row) * DH + c2);
        acc.x += v.x; acc.y += v.y;
    }
    float inv = 1.f / l;
    int h = row >> 12, b = row & (BATCH - 1);
    float2 r = make_float2(acc.x * inv, acc.y * inv);
    *(float2*)(out + b * (HEADS * DH) + h * DH + c2) = r;
}

extern "C" void kernel_launch(void* const* d_in, const int* in_sizes, int n_in,
                              void* d_out, int out_size)
{
    const float* q  = (const float*)d_in[0];
    const float* k  = (const float*)d_in[1];
    const float* v  = (const float*)d_in[2];
    const float* wq = (const float*)d_in[3];
    const float* wk = (const float*)d_in[4];
    const float* wv = (const float*)d_in[5];
    float* out = (float*)d_out;

    cudaFuncSetAttribute(flash_mma_kernel,
                         cudaFuncAttributeMaxDynamicSharedMemorySize, SMEM_TOTAL);

    // Q scale = 1/sqrt(64) * log2(e), folded into Wq during conversion.
    dim3 cgrid((BATCH * EMBED / 4 + 255) / 256, 6);
    convert_kernel<<<cgrid, 256>>>(q, k, v, wq, wk, wv, 0.125f * 1.44269504f);

    dim3 pgrid(BATCH / 64, (HEADS * DH) / 64, 3);
    proj_mma_kernel<<<pgrid, 64>>>();

    dim3 fgrid(HB / MROWS, KS);
    flash_mma_kernel<<<fgrid, 64, SMEM_TOTAL>>>();

    combine_kernel<<<(HB * DH / 2) / 256, 256>>>(out);
}